// round 8
// baseline (speedup 1.0000x reference)
#include <cuda_runtime.h>
#include <cstdint>

// Problem constants (fixed by the reference)
#define BB 16
#define NN 8192
#define MM 2048
#define KK 32
#define CC 128

#define CTAS 1184   // 148 SMs * 8 resident CTAs -> exactly one persistent wave

// out layout: [pts (B*M*K*3 floats)] ++ [features (B*M*K*C floats)]
//
// Persistent-CTA version of the converged inner structure:
//   grid = 1184 CTAs x 256 threads, each CTA grid-strides over bm.
//   Per iteration (identical to the best per-CTA kernel):
//    - each warp loads the 32 indices coalesced (lane k = index k),
//      broadcasts per-row indices with __shfl_sync; no smem, no barrier.
//    - warp 0 computes the normalized relative coords (lane = k).
//    - warp w copies rows {4w..4w+3}, interleaved LDG.128 -> STG.128
//      (low MLP_p1 on purpose; front-batching measurably hurt).
//   Successive iterations are independent, so load latency of iteration
//   i+1 overlaps the store tail of iteration i — removing the per-CTA
//   launch/drain churn of the 27.7-wave grid.
__global__ __launch_bounds__(256, 8)
void knn_gather_norm_v7_kernel(const float* __restrict__ input,      // [B,N,C]
                               const float* __restrict__ points,     // [B,N,3]
                               const float* __restrict__ next_pts,   // [B,M,3]
                               const int*   __restrict__ indices,    // [B,M,K]
                               float* __restrict__ out_pts,          // [B,M,K,3]
                               float* __restrict__ out_feat)         // [B,M,K,C]
{
    const int tid  = threadIdx.x;
    const int wid  = tid >> 5;
    const int lane = tid & 31;

    for (int bm = blockIdx.x; bm < BB * MM; bm += CTAS) {
        const int b = bm / MM;

        // lane k holds neighbor index k for this bm (coalesced 128B load;
        // warps 1..7 hit L1 on warp 0's line)
        const int myidx = __ldg(&indices[(size_t)bm * KK + lane]);

        // ---- pts: warp 0, lane = neighbor k ----
        if (wid == 0) {
            const float nx = __ldg(&next_pts[(size_t)bm * 3 + 0]);
            const float ny = __ldg(&next_pts[(size_t)bm * 3 + 1]);
            const float nz = __ldg(&next_pts[(size_t)bm * 3 + 2]);

            const float* p = points + ((size_t)b * NN + (size_t)myidx) * 3;
            const float dx = __ldg(&p[0]) - nx;
            const float dy = __ldg(&p[1]) - ny;
            const float dz = __ldg(&p[2]) - nz;

            float mx = dx * dx + dy * dy + dz * dz;
            #pragma unroll
            for (int o = 16; o > 0; o >>= 1)
                mx = fmaxf(mx, __shfl_xor_sync(0xffffffffu, mx, o));

            float maxi = sqrtf(mx);
            if (maxi == 0.0f) maxi = 1.0f;
            const float inv = 1.0f / maxi;

            float* o = out_pts + ((size_t)bm * KK + (size_t)lane) * 3;
            o[0] = dx * inv;
            o[1] = dy * inv;
            o[2] = dz * inv;
        }

        // ---- features: warp wid owns rows {4*wid .. 4*wid+3}, interleaved ----
        const float* __restrict__ in_b = input + (size_t)b * NN * CC;
        float4* __restrict__ of =
            reinterpret_cast<float4*>(out_feat + (size_t)bm * KK * CC);

        #pragma unroll
        for (int j = 0; j < 4; ++j) {
            const int k   = 4 * wid + j;
            const int idx = __shfl_sync(0xffffffffu, myidx, k);
            const float4 v =
                __ldg(reinterpret_cast<const float4*>(in_b + (size_t)idx * CC) + lane);
            of[(size_t)k * (CC / 4) + lane] = v;
        }
    }
}

extern "C" void kernel_launch(void* const* d_in, const int* in_sizes, int n_in,
                              void* d_out, int out_size)
{
    const float* input    = (const float*)d_in[0];  // [B,N,C]
    const float* points   = (const float*)d_in[1];  // [B,N,3]
    const float* next_pts = (const float*)d_in[2];  // [B,M,3]
    const int*   indices  = (const int*)  d_in[3];  // [B,M,K]

    float* out_pts  = (float*)d_out;                         // B*M*K*3
    float* out_feat = out_pts + (size_t)BB * MM * KK * 3;    // B*M*K*C

    knn_gather_norm_v7_kernel<<<CTAS, 256>>>(input, points, next_pts, indices,
                                             out_pts, out_feat);
}

// round 9
// speedup vs baseline: 1.3417x; 1.3417x over previous
#include <cuda_runtime.h>
#include <cstdint>

// Problem constants (fixed by the reference)
#define BB 16
#define NN 8192
#define MM 2048
#define KK 32
#define CC 128

// out layout: [pts (B*M*K*3 floats)] ++ [features (B*M*K*C floats)]
//
// One CTA per (b, m). 288 threads = 9 warps:
//  - warps 0..7: uniform copiers, 4 feature rows each, paired interleave
//    (2 loads in flight, then 2 stores -> MLP_p1=2, at the safe knee).
//  - warp 8: dedicated pts warp (lane = neighbor k) — removes the serial
//    normalization chain from the copy warps' critical path.
// No smem, no __syncthreads; indices loaded coalesced per warp (lane k =
// index k, one 128B line, L1-broadcast across warps) + __shfl_sync.
__global__ __launch_bounds__(288, 7)
void knn_gather_norm_v9_kernel(const float* __restrict__ input,      // [B,N,C]
                               const float* __restrict__ points,     // [B,N,3]
                               const float* __restrict__ next_pts,   // [B,M,3]
                               const int*   __restrict__ indices,    // [B,M,K]
                               float* __restrict__ out_pts,          // [B,M,K,3]
                               float* __restrict__ out_feat)         // [B,M,K,C]
{
    const int bm = blockIdx.x;            // 0 .. B*M-1
    const int b  = bm / MM;

    const int tid  = threadIdx.x;
    const int wid  = tid >> 5;
    const int lane = tid & 31;

    // lane k holds neighbor index k for this bm
    const int myidx = __ldg(&indices[(size_t)bm * KK + lane]);

    if (wid == 8) {
        // ---- pts warp: lane = neighbor k ----
        const float nx = __ldg(&next_pts[(size_t)bm * 3 + 0]);
        const float ny = __ldg(&next_pts[(size_t)bm * 3 + 1]);
        const float nz = __ldg(&next_pts[(size_t)bm * 3 + 2]);

        const float* p = points + ((size_t)b * NN + (size_t)myidx) * 3;
        const float dx = __ldg(&p[0]) - nx;
        const float dy = __ldg(&p[1]) - ny;
        const float dz = __ldg(&p[2]) - nz;

        float mx = dx * dx + dy * dy + dz * dz;
        #pragma unroll
        for (int o = 16; o > 0; o >>= 1)
            mx = fmaxf(mx, __shfl_xor_sync(0xffffffffu, mx, o));

        float maxi = sqrtf(mx);
        if (maxi == 0.0f) maxi = 1.0f;
        const float inv = 1.0f / maxi;

        float* o = out_pts + ((size_t)bm * KK + (size_t)lane) * 3;
        o[0] = dx * inv;
        o[1] = dy * inv;
        o[2] = dz * inv;
    } else {
        // ---- copy warps: warp wid owns rows {4*wid .. 4*wid+3} ----
        const float* __restrict__ in_b = input + (size_t)b * NN * CC;
        float4* __restrict__ of =
            reinterpret_cast<float4*>(out_feat + (size_t)bm * KK * CC);

        const int k0 = 4 * wid;
        #pragma unroll
        for (int j = 0; j < 4; j += 2) {
            const int ia = __shfl_sync(0xffffffffu, myidx, k0 + j);
            const int ib = __shfl_sync(0xffffffffu, myidx, k0 + j + 1);

            const float4 va =
                __ldg(reinterpret_cast<const float4*>(in_b + (size_t)ia * CC) + lane);
            const float4 vb =
                __ldg(reinterpret_cast<const float4*>(in_b + (size_t)ib * CC) + lane);

            of[(size_t)(k0 + j)     * (CC / 4) + lane] = va;
            of[(size_t)(k0 + j + 1) * (CC / 4) + lane] = vb;
        }
    }
}

extern "C" void kernel_launch(void* const* d_in, const int* in_sizes, int n_in,
                              void* d_out, int out_size)
{
    const float* input    = (const float*)d_in[0];  // [B,N,C]
    const float* points   = (const float*)d_in[1];  // [B,N,3]
    const float* next_pts = (const float*)d_in[2];  // [B,M,3]
    const int*   indices  = (const int*)  d_in[3];  // [B,M,K]

    float* out_pts  = (float*)d_out;                         // B*M*K*3
    float* out_feat = out_pts + (size_t)BB * MM * KK * 3;    // B*M*K*C

    const int grid = BB * MM;   // 32768 CTAs
    knn_gather_norm_v9_kernel<<<grid, 288>>>(input, points, next_pts, indices,
                                             out_pts, out_feat);
}

// round 10
// speedup vs baseline: 1.4263x; 1.0631x over previous
#include <cuda_runtime.h>
#include <cstdint>

// Problem constants (fixed by the reference)
#define BB 16
#define NN 8192
#define MM 2048
#define KK 32
#define CC 128

// out layout: [pts (B*M*K*3 floats)] ++ [features (B*M*K*C floats)]
//
// R1 structure (best so far: 96.3us) with ONE change: 128-thread CTAs.
// One CTA per (b, m), 4 warps:
//  - warp 0: normalized relative coords for all K=32 neighbors (lane = k)
//  - warp w copies rows {w, w+4, ..., w+28}: strict per-row LDG.128 -> STG.128
//    interleave (every attempt to batch/pair loads or restructure lost).
// 16 resident CTAs/SM (vs 8 at 256 thr): desynchronizes the per-CTA
// startup bubbles so the SM's store stream has fewer aligned gaps.
__global__ __launch_bounds__(128, 16)
void knn_gather_norm_v10_kernel(const float* __restrict__ input,      // [B,N,C]
                                const float* __restrict__ points,     // [B,N,3]
                                const float* __restrict__ next_pts,   // [B,M,3]
                                const int*   __restrict__ indices,    // [B,M,K]
                                float* __restrict__ out_pts,          // [B,M,K,3]
                                float* __restrict__ out_feat)         // [B,M,K,C]
{
    const int bm = blockIdx.x;            // 0 .. B*M-1
    const int b  = bm / MM;

    __shared__ int sidx[KK];

    const int tid  = threadIdx.x;
    const int wid  = tid >> 5;
    const int lane = tid & 31;

    if (tid < KK) {
        sidx[tid] = indices[(size_t)bm * KK + tid];
    }
    __syncthreads();

    // ---- pts: warp 0, lane = neighbor k ----
    if (wid == 0) {
        const int k   = lane;
        const int idx = sidx[k];

        const float nx = __ldg(&next_pts[(size_t)bm * 3 + 0]);
        const float ny = __ldg(&next_pts[(size_t)bm * 3 + 1]);
        const float nz = __ldg(&next_pts[(size_t)bm * 3 + 2]);

        const float* p = points + ((size_t)b * NN + (size_t)idx) * 3;
        const float dx = __ldg(&p[0]) - nx;
        const float dy = __ldg(&p[1]) - ny;
        const float dz = __ldg(&p[2]) - nz;

        float mx = dx * dx + dy * dy + dz * dz;
        #pragma unroll
        for (int o = 16; o > 0; o >>= 1)
            mx = fmaxf(mx, __shfl_xor_sync(0xffffffffu, mx, o));

        float maxi = sqrtf(mx);
        if (maxi == 0.0f) maxi = 1.0f;
        const float inv = 1.0f / maxi;

        float* o = out_pts + ((size_t)bm * KK + (size_t)k) * 3;
        o[0] = dx * inv;
        o[1] = dy * inv;
        o[2] = dz * inv;
    }

    // ---- features: warp wid owns rows {wid, wid+4, ..., wid+28} ----
    #pragma unroll
    for (int k = wid; k < KK; k += 4) {
        const int idx = sidx[k];
        const float4* __restrict__ src =
            reinterpret_cast<const float4*>(input + ((size_t)b * NN + (size_t)idx) * CC);
        float4* __restrict__ dst =
            reinterpret_cast<float4*>(out_feat + ((size_t)bm * KK + (size_t)k) * CC);
        dst[lane] = src[lane];
    }
}

extern "C" void kernel_launch(void* const* d_in, const int* in_sizes, int n_in,
                              void* d_out, int out_size)
{
    const float* input    = (const float*)d_in[0];  // [B,N,C]
    const float* points   = (const float*)d_in[1];  // [B,N,3]
    const float* next_pts = (const float*)d_in[2];  // [B,M,3]
    const int*   indices  = (const int*)  d_in[3];  // [B,M,K]

    float* out_pts  = (float*)d_out;                         // B*M*K*3
    float* out_feat = out_pts + (size_t)BB * MM * KK * 3;    // B*M*K*C

    const int grid = BB * MM;   // 32768 CTAs
    knn_gather_norm_v10_kernel<<<grid, 128>>>(input, points, next_pts, indices,
                                              out_pts, out_feat);
}

// round 11
// speedup vs baseline: 1.4277x; 1.0010x over previous
#include <cuda_runtime.h>
#include <cstdint>

// Problem constants (fixed by the reference)
#define BB 16
#define NN 8192
#define MM 2048
#define KK 32
#define CC 128

// out layout: [pts (B*M*K*3 floats)] ++ [features (B*M*K*C floats)]
//
// R1 structure (best so far: 96.3us) with ONE change: 128-thread CTAs.
// One CTA per (b, m), 4 warps:
//  - warp 0: normalized relative coords for all K=32 neighbors (lane = k)
//  - warp w copies rows {w, w+4, ..., w+28}: strict per-row LDG.128 -> STG.128
//    interleave (every attempt to batch/pair loads or restructure lost).
// 16 resident CTAs/SM (vs 8 at 256 thr): desynchronizes the per-CTA
// startup bubbles so the SM's store stream has fewer aligned gaps.
__global__ __launch_bounds__(128, 16)
void knn_gather_norm_v10_kernel(const float* __restrict__ input,      // [B,N,C]
                                const float* __restrict__ points,     // [B,N,3]
                                const float* __restrict__ next_pts,   // [B,M,3]
                                const int*   __restrict__ indices,    // [B,M,K]
                                float* __restrict__ out_pts,          // [B,M,K,3]
                                float* __restrict__ out_feat)         // [B,M,K,C]
{
    const int bm = blockIdx.x;            // 0 .. B*M-1
    const int b  = bm / MM;

    __shared__ int sidx[KK];

    const int tid  = threadIdx.x;
    const int wid  = tid >> 5;
    const int lane = tid & 31;

    if (tid < KK) {
        sidx[tid] = indices[(size_t)bm * KK + tid];
    }
    __syncthreads();

    // ---- pts: warp 0, lane = neighbor k ----
    if (wid == 0) {
        const int k   = lane;
        const int idx = sidx[k];

        const float nx = __ldg(&next_pts[(size_t)bm * 3 + 0]);
        const float ny = __ldg(&next_pts[(size_t)bm * 3 + 1]);
        const float nz = __ldg(&next_pts[(size_t)bm * 3 + 2]);

        const float* p = points + ((size_t)b * NN + (size_t)idx) * 3;
        const float dx = __ldg(&p[0]) - nx;
        const float dy = __ldg(&p[1]) - ny;
        const float dz = __ldg(&p[2]) - nz;

        float mx = dx * dx + dy * dy + dz * dz;
        #pragma unroll
        for (int o = 16; o > 0; o >>= 1)
            mx = fmaxf(mx, __shfl_xor_sync(0xffffffffu, mx, o));

        float maxi = sqrtf(mx);
        if (maxi == 0.0f) maxi = 1.0f;
        const float inv = 1.0f / maxi;

        float* o = out_pts + ((size_t)bm * KK + (size_t)k) * 3;
        o[0] = dx * inv;
        o[1] = dy * inv;
        o[2] = dz * inv;
    }

    // ---- features: warp wid owns rows {wid, wid+4, ..., wid+28} ----
    #pragma unroll
    for (int k = wid; k < KK; k += 4) {
        const int idx = sidx[k];
        const float4* __restrict__ src =
            reinterpret_cast<const float4*>(input + ((size_t)b * NN + (size_t)idx) * CC);
        float4* __restrict__ dst =
            reinterpret_cast<float4*>(out_feat + ((size_t)bm * KK + (size_t)k) * CC);
        dst[lane] = src[lane];
    }
}

extern "C" void kernel_launch(void* const* d_in, const int* in_sizes, int n_in,
                              void* d_out, int out_size)
{
    const float* input    = (const float*)d_in[0];  // [B,N,C]
    const float* points   = (const float*)d_in[1];  // [B,N,3]
    const float* next_pts = (const float*)d_in[2];  // [B,M,3]
    const int*   indices  = (const int*)  d_in[3];  // [B,M,K]

    float* out_pts  = (float*)d_out;                         // B*M*K*3
    float* out_feat = out_pts + (size_t)BB * MM * KK * 3;    // B*M*K*C

    const int grid = BB * MM;   // 32768 CTAs
    knn_gather_norm_v10_kernel<<<grid, 128>>>(input, points, next_pts, indices,
                                              out_pts, out_feat);
}